// round 1
// baseline (speedup 1.0000x reference)
#include <cuda_runtime.h>
#include <math.h>

// Problem dims (fixed by reference)
#define Bn  32
#define Ln  1024
#define Dn  512
#define Hn  8
#define DHn 64

#define NEGC (-4294967295.0f)   // -2^32 + 1, matches reference padding value

// Scratch (allocation-free rule: static __device__ globals)
__device__ float g_Q[(size_t)Bn * Ln * Dn];
__device__ float g_K[(size_t)Bn * Ln * Dn];
__device__ float g_V[(size_t)Bn * Ln * Dn];
__device__ float g_kmask[Bn * Ln];
__device__ float g_qmask[Bn * Ln];

// ---------------------------------------------------------------------------
// Padding masks: mask[row] = (sum over D features != 0) ? 1 : 0
// One warp per row; 65536 rows total (queries then keys).
// ---------------------------------------------------------------------------
__global__ void mask_kernel(const float* __restrict__ queries,
                            const float* __restrict__ keys) {
    int warp = (blockIdx.x * blockDim.x + threadIdx.x) >> 5;
    int lane = threadIdx.x & 31;
    int which = warp >> 15;            // 0 = queries, 1 = keys
    int row = warp & (Bn * Ln - 1);
    const float* src = which ? keys : queries;
    const float4* p = (const float4*)(src + (size_t)row * Dn);
    float s = 0.f;
#pragma unroll
    for (int i = 0; i < 4; i++) {
        float4 v = p[lane + 32 * i];
        s += (v.x + v.y) + (v.z + v.w);
    }
#pragma unroll
    for (int o = 16; o; o >>= 1) s += __shfl_xor_sync(0xffffffffu, s, o);
    if (lane == 0) {
        float m = (s != 0.0f) ? 1.0f : 0.0f;
        if (which) g_kmask[row] = m; else g_qmask[row] = m;
    }
}

// ---------------------------------------------------------------------------
// C[M=32768, N=512] = A[M, K=512] @ W[N, K]^T + bias[N]   (torch Linear)
// 128x128x16 block tile, 8x8 register tile, 256 threads.
// ---------------------------------------------------------------------------
__global__ void __launch_bounds__(256) gemm_qkv(const float* __restrict__ A,
                                                const float* __restrict__ W,
                                                const float* __restrict__ bias,
                                                float* __restrict__ C) {
    __shared__ float As[16][132];   // [k][m]
    __shared__ float Bs[16][132];   // [k][n]
    const int K = Dn, N = Dn;
    int tid = threadIdx.x;
    int bm = blockIdx.y * 128;
    int bn = blockIdx.x * 128;
    int lr = tid >> 2;            // 0..63
    int lk = (tid & 3) * 4;       // 0,4,8,12
    int ty = tid >> 4;            // 0..15
    int tx = tid & 15;            // 0..15

    const float* Ap0 = A + (size_t)(bm + lr) * K + lk;
    const float* Ap1 = A + (size_t)(bm + lr + 64) * K + lk;
    const float* Wp0 = W + (size_t)(bn + lr) * K + lk;
    const float* Wp1 = W + (size_t)(bn + lr + 64) * K + lk;

    float acc[8][8];
#pragma unroll
    for (int i = 0; i < 8; i++)
#pragma unroll
        for (int j = 0; j < 8; j++) acc[i][j] = 0.f;

    for (int k0 = 0; k0 < K; k0 += 16) {
        float4 a0 = *(const float4*)(Ap0 + k0);
        float4 a1 = *(const float4*)(Ap1 + k0);
        float4 b0 = *(const float4*)(Wp0 + k0);
        float4 b1 = *(const float4*)(Wp1 + k0);
        __syncthreads();
        As[lk + 0][lr] = a0.x; As[lk + 1][lr] = a0.y;
        As[lk + 2][lr] = a0.z; As[lk + 3][lr] = a0.w;
        As[lk + 0][lr + 64] = a1.x; As[lk + 1][lr + 64] = a1.y;
        As[lk + 2][lr + 64] = a1.z; As[lk + 3][lr + 64] = a1.w;
        Bs[lk + 0][lr] = b0.x; Bs[lk + 1][lr] = b0.y;
        Bs[lk + 2][lr] = b0.z; Bs[lk + 3][lr] = b0.w;
        Bs[lk + 0][lr + 64] = b1.x; Bs[lk + 1][lr + 64] = b1.y;
        Bs[lk + 2][lr + 64] = b1.z; Bs[lk + 3][lr + 64] = b1.w;
        __syncthreads();
#pragma unroll
        for (int kk = 0; kk < 16; kk++) {
            float4 xa0 = *(const float4*)&As[kk][ty * 4];
            float4 xa1 = *(const float4*)&As[kk][ty * 4 + 64];
            float4 xb0 = *(const float4*)&Bs[kk][tx * 4];
            float4 xb1 = *(const float4*)&Bs[kk][tx * 4 + 64];
            float av[8] = {xa0.x, xa0.y, xa0.z, xa0.w, xa1.x, xa1.y, xa1.z, xa1.w};
            float bv[8] = {xb0.x, xb0.y, xb0.z, xb0.w, xb1.x, xb1.y, xb1.z, xb1.w};
#pragma unroll
            for (int i = 0; i < 8; i++)
#pragma unroll
                for (int j = 0; j < 8; j++) acc[i][j] += av[i] * bv[j];
        }
    }

    float4 bb0 = *(const float4*)(bias + bn + tx * 4);
    float4 bb1 = *(const float4*)(bias + bn + tx * 4 + 64);
    float bcol[8] = {bb0.x, bb0.y, bb0.z, bb0.w, bb1.x, bb1.y, bb1.z, bb1.w};
#pragma unroll
    for (int i = 0; i < 8; i++) {
        int row = bm + ((i < 4) ? (ty * 4 + i) : (64 + ty * 4 + i - 4));
        float* crow = C + (size_t)row * N + bn;
        float4 o0, o1;
        o0.x = acc[i][0] + bcol[0]; o0.y = acc[i][1] + bcol[1];
        o0.z = acc[i][2] + bcol[2]; o0.w = acc[i][3] + bcol[3];
        o1.x = acc[i][4] + bcol[4]; o1.y = acc[i][5] + bcol[5];
        o1.z = acc[i][6] + bcol[6]; o1.w = acc[i][7] + bcol[7];
        *(float4*)(crow + tx * 4) = o0;
        *(float4*)(crow + tx * 4 + 64) = o1;
    }
}

// ---------------------------------------------------------------------------
// Causal flash attention, one block per (q_tile=64, head, batch).
// 64x64 S tile, 4x4 register tiles, online softmax, fused mask + residual.
// ---------------------------------------------------------------------------
#define ATTN_SMEM (4 * 64 * 68 * 4)

__global__ void __launch_bounds__(256) attn_kernel(const float* __restrict__ queries,
                                                   float* __restrict__ out) {
    extern __shared__ float sm[];
    float* Qs = sm;                   // [k][r], stride 68
    float* Ks = sm + 64 * 68;         // [k][c]
    float* Vs = sm + 2 * 64 * 68;     // [j][d]
    float* Ps = sm + 3 * 64 * 68;     // [j][r]

    const int L = Ln, D = Dn;
    int qt = blockIdx.x, h = blockIdx.y, b = blockIdx.z;
    int tid = threadIdx.x;
    int ty = tid >> 4, tx = tid & 15;
    int r0 = ty * 4, c0 = tx * 4;
    int q0 = qt * 64;

    int lr = tid >> 2;              // 0..63 (row for cooperative loads)
    int lk = (tid & 3) * 4;         // 0,4,8,12 (k offset, +16*i)

    // Load Q tile (transposed to k-major), pre-scaled by 1/sqrt(depth)
    {
        const float* qr = g_Q + ((size_t)(b * L + q0 + lr)) * D + h * DHn;
#pragma unroll
        for (int i = 0; i < 4; i++) {
            int kk = lk + 16 * i;
            float4 v = *(const float4*)(qr + kk);
            Qs[(kk + 0) * 68 + lr] = v.x * 0.125f;
            Qs[(kk + 1) * 68 + lr] = v.y * 0.125f;
            Qs[(kk + 2) * 68 + lr] = v.z * 0.125f;
            Qs[(kk + 3) * 68 + lr] = v.w * 0.125f;
        }
    }

    float acc[4][4];
#pragma unroll
    for (int i = 0; i < 4; i++)
#pragma unroll
        for (int j = 0; j < 4; j++) acc[i][j] = 0.f;
    float mrow[4], lsum[4];
#pragma unroll
    for (int i = 0; i < 4; i++) { mrow[i] = -INFINITY; lsum[i] = 0.f; }

    int ntiles = qt + 1;   // causal: only tiles with keys <= queries
    for (int kt = 0; kt < ntiles; kt++) {
        int kg0 = kt * 64;
        __syncthreads();   // prior-iter reads of Ks/Vs/Ps done
        {
            const float* kr = g_K + ((size_t)(b * L + kg0 + lr)) * D + h * DHn;
            const float* vr = g_V + ((size_t)(b * L + kg0 + lr)) * D + h * DHn;
#pragma unroll
            for (int i = 0; i < 4; i++) {
                int kk = lk + 16 * i;
                float4 kv = *(const float4*)(kr + kk);
                Ks[(kk + 0) * 68 + lr] = kv.x;
                Ks[(kk + 1) * 68 + lr] = kv.y;
                Ks[(kk + 2) * 68 + lr] = kv.z;
                Ks[(kk + 3) * 68 + lr] = kv.w;
                float4 vv = *(const float4*)(vr + kk);
                *(float4*)&Vs[lr * 68 + kk] = vv;
            }
        }
        __syncthreads();

        // S = (Q/8) K^T  (4x4 per thread)
        float s[4][4];
#pragma unroll
        for (int i = 0; i < 4; i++)
#pragma unroll
            for (int j = 0; j < 4; j++) s[i][j] = 0.f;
#pragma unroll 8
        for (int k = 0; k < 64; k++) {
            float4 a = *(const float4*)&Qs[k * 68 + r0];
            float4 bb = *(const float4*)&Ks[k * 68 + c0];
            float av[4] = {a.x, a.y, a.z, a.w};
            float bv[4] = {bb.x, bb.y, bb.z, bb.w};
#pragma unroll
            for (int i = 0; i < 4; i++)
#pragma unroll
                for (int j = 0; j < 4; j++) s[i][j] += av[i] * bv[j];
        }

        // key-padding + causal masks (finite NEG, matching reference)
        bool diag = (kt == qt);
#pragma unroll
        for (int j = 0; j < 4; j++) {
            int jg = kg0 + c0 + j;
            float km = g_kmask[b * L + jg];
            bool kvalid = (km != 0.0f);
#pragma unroll
            for (int i = 0; i < 4; i++) {
                bool ok = kvalid && (!diag || jg <= (q0 + r0 + i));
                if (!ok) s[i][j] = NEGC;
            }
        }

        // Online softmax (row reductions across the 16 lanes sharing a row)
#pragma unroll
        for (int i = 0; i < 4; i++) {
            float mx = fmaxf(fmaxf(s[i][0], s[i][1]), fmaxf(s[i][2], s[i][3]));
#pragma unroll
            for (int o = 8; o; o >>= 1) mx = fmaxf(mx, __shfl_xor_sync(0xffffffffu, mx, o));
            float mnew = fmaxf(mrow[i], mx);
            float corr = __expf(mrow[i] - mnew);
            mrow[i] = mnew;
            float ps = 0.f;
#pragma unroll
            for (int j = 0; j < 4; j++) {
                float p = __expf(s[i][j] - mnew);
                s[i][j] = p;
                ps += p;
            }
#pragma unroll
            for (int o = 8; o; o >>= 1) ps += __shfl_xor_sync(0xffffffffu, ps, o);
            lsum[i] = lsum[i] * corr + ps;
#pragma unroll
            for (int j = 0; j < 4; j++) acc[i][j] *= corr;
        }

        // Write P transposed: Ps[j][r]
#pragma unroll
        for (int j = 0; j < 4; j++) {
            float4 pv = make_float4(s[0][j], s[1][j], s[2][j], s[3][j]);
            *(float4*)&Ps[(c0 + j) * 68 + r0] = pv;
        }
        __syncthreads();

        // acc += P @ V
#pragma unroll 8
        for (int j = 0; j < 64; j++) {
            float4 p4 = *(const float4*)&Ps[j * 68 + r0];
            float4 v4 = *(const float4*)&Vs[j * 68 + c0];
            float pv[4] = {p4.x, p4.y, p4.z, p4.w};
            float vv[4] = {v4.x, v4.y, v4.z, v4.w};
#pragma unroll
            for (int i = 0; i < 4; i++)
#pragma unroll
                for (int jj = 0; jj < 4; jj++) acc[i][jj] += pv[i] * vv[jj];
        }
    }

    // Epilogue: normalize, query mask, residual add
#pragma unroll
    for (int i = 0; i < 4; i++) {
        int qg = q0 + r0 + i;
        float qm = g_qmask[b * L + qg];
        float f = qm / lsum[i];
        size_t off = ((size_t)(b * L + qg)) * D + h * DHn + c0;
        float4 rv = *(const float4*)(queries + off);
        float4 o;
        o.x = acc[i][0] * f + rv.x;
        o.y = acc[i][1] * f + rv.y;
        o.z = acc[i][2] * f + rv.z;
        o.w = acc[i][3] * f + rv.w;
        *(float4*)(out + off) = o;
    }
}

// ---------------------------------------------------------------------------
extern "C" void kernel_launch(void* const* d_in, const int* in_sizes, int n_in,
                              void* d_out, int out_size) {
    (void)in_sizes; (void)n_in; (void)out_size;
    const float* queries = (const float*)d_in[0];
    const float* keys    = (const float*)d_in[1];
    const float* Wq = (const float*)d_in[2];
    const float* bq = (const float*)d_in[3];
    const float* Wk = (const float*)d_in[4];
    const float* bk = (const float*)d_in[5];
    const float* Wv = (const float*)d_in[6];
    const float* bv = (const float*)d_in[7];
    float* out = (float*)d_out;

    float *qp, *kp, *vp;
    cudaGetSymbolAddress((void**)&qp, g_Q);
    cudaGetSymbolAddress((void**)&kp, g_K);
    cudaGetSymbolAddress((void**)&vp, g_V);

    cudaFuncSetAttribute(attn_kernel,
                         cudaFuncAttributeMaxDynamicSharedMemorySize, ATTN_SMEM);

    mask_kernel<<<8192, 256>>>(queries, keys);
    dim3 gg(4, 256);
    gemm_qkv<<<gg, 256>>>(queries, Wq, bq, qp);
    gemm_qkv<<<gg, 256>>>(keys,    Wk, bk, kp);
    gemm_qkv<<<gg, 256>>>(keys,    Wv, bv, vp);
    attn_kernel<<<dim3(16, 8, 32), 256, ATTN_SMEM>>>(queries, out);
}

// round 3
// speedup vs baseline: 1.3218x; 1.3218x over previous
#include <cuda_runtime.h>
#include <cuda_bf16.h>
#include <math.h>
#include <cstdint>

// Problem dims (fixed by reference)
#define Bn  32
#define Ln  1024
#define Dn  512
#define Hn  8
#define DHn 64

#define NEGC (-4294967295.0f)   // -2^32 + 1, matches reference padding value

// ---------------------------------------------------------------------------
// Scratch (allocation-free rule: static __device__ globals)
// ---------------------------------------------------------------------------
__device__ float g_Q[(size_t)Bn * Ln * Dn];
__device__ float g_K[(size_t)Bn * Ln * Dn];
__device__ float g_V[(size_t)Bn * Ln * Dn];
__device__ float g_kmask[Bn * Ln];
__device__ float g_qmask[Bn * Ln];

// bf16 split (hi+lo) copies of GEMM operands
#define NELEM_A ((size_t)Bn * Ln * Dn)      // 16,777,216
#define NELEM_W ((size_t)Dn * Dn)           // 262,144
__device__ __nv_bfloat16 g_qhi[NELEM_A];
__device__ __nv_bfloat16 g_qlo[NELEM_A];
__device__ __nv_bfloat16 g_khi[NELEM_A];
__device__ __nv_bfloat16 g_klo[NELEM_A];
__device__ __nv_bfloat16 g_whi[3][NELEM_W];
__device__ __nv_bfloat16 g_wlo[3][NELEM_W];

// ---------------------------------------------------------------------------
// PTX helpers (sm_80-baseline only — tcgen05 does NOT assemble at .target
// sm_103 in this harness)
// ---------------------------------------------------------------------------
__device__ __forceinline__ uint32_t smem_u32(const void* p) {
    uint32_t a;
    asm("{ .reg .u64 t; cvta.to.shared.u64 t, %1; cvt.u32.u64 %0, t; }"
        : "=r"(a) : "l"(p));
    return a;
}
__device__ __forceinline__ void cp16(uint32_t dst, const void* src) {
    asm volatile("cp.async.cg.shared.global [%0], [%1], 16;\n"
                 :: "r"(dst), "l"(src) : "memory");
}
#define CP_COMMIT() asm volatile("cp.async.commit_group;\n" ::: "memory")

__device__ __forceinline__ void ldsm_x4(uint32_t* r, uint32_t addr) {
    asm volatile("ldmatrix.sync.aligned.m8n8.x4.shared.b16 {%0,%1,%2,%3}, [%4];"
                 : "=r"(r[0]), "=r"(r[1]), "=r"(r[2]), "=r"(r[3]) : "r"(addr));
}
__device__ __forceinline__ void mma16816(float* d, const uint32_t* a, const uint32_t* b) {
    asm volatile(
        "mma.sync.aligned.m16n8k16.row.col.f32.bf16.bf16.f32 "
        "{%0,%1,%2,%3}, {%4,%5,%6,%7}, {%8,%9}, {%0,%1,%2,%3};"
        : "+f"(d[0]), "+f"(d[1]), "+f"(d[2]), "+f"(d[3])
        : "r"(a[0]), "r"(a[1]), "r"(a[2]), "r"(a[3]), "r"(b[0]), "r"(b[1]));
}

// ---------------------------------------------------------------------------
// Padding masks: mask[row] = (sum over D features != 0) ? 1 : 0
// ---------------------------------------------------------------------------
__global__ void mask_kernel(const float* __restrict__ queries,
                            const float* __restrict__ keys) {
    int warp = (blockIdx.x * blockDim.x + threadIdx.x) >> 5;
    int lane = threadIdx.x & 31;
    int which = warp >> 15;            // 0 = queries, 1 = keys
    int row = warp & (Bn * Ln - 1);
    const float* src = which ? keys : queries;
    const float4* p = (const float4*)(src + (size_t)row * Dn);
    float s = 0.f;
#pragma unroll
    for (int i = 0; i < 4; i++) {
        float4 v = p[lane + 32 * i];
        s += (v.x + v.y) + (v.z + v.w);
    }
#pragma unroll
    for (int o = 16; o; o >>= 1) s += __shfl_xor_sync(0xffffffffu, s, o);
    if (lane == 0) {
        float m = (s != 0.0f) ? 1.0f : 0.0f;
        if (which) g_kmask[row] = m; else g_qmask[row] = m;
    }
}

// ---------------------------------------------------------------------------
// fp32 -> bf16 (hi, lo) split conversion
// ---------------------------------------------------------------------------
__global__ void cvt_kernel(const float* __restrict__ src,
                           __nv_bfloat16* __restrict__ hi,
                           __nv_bfloat16* __restrict__ lo, int n4) {
    int i = blockIdx.x * blockDim.x + threadIdx.x;
    if (i >= n4) return;
    float4 v = ((const float4*)src)[i];
    __nv_bfloat162 h0 = __floats2bfloat162_rn(v.x, v.y);
    __nv_bfloat162 h1 = __floats2bfloat162_rn(v.z, v.w);
    float2 f0 = __bfloat1622float2(h0);
    float2 f1 = __bfloat1622float2(h1);
    __nv_bfloat162 l0 = __floats2bfloat162_rn(v.x - f0.x, v.y - f0.y);
    __nv_bfloat162 l1 = __floats2bfloat162_rn(v.z - f1.x, v.w - f1.y);
    ((__nv_bfloat162*)hi)[2 * i + 0] = h0;
    ((__nv_bfloat162*)hi)[2 * i + 1] = h1;
    ((__nv_bfloat162*)lo)[2 * i + 0] = l0;
    ((__nv_bfloat162*)lo)[2 * i + 1] = l1;
}

// ---------------------------------------------------------------------------
// bf16-split GEMM on mma.sync: out[M=32768, N=512] = A @ W^T + bias
// CTA tile 128x128, K chunks of 32, 8 warps (warp tile 32x64).
// D = Ahi*Whi + Ahi*Wlo + Alo*Whi (3 HMMAs per fragment pair).
// SMEM: 4 matrices per stage (Ahi, Alo, Whi, Wlo), 128 rows x 32 bf16,
// row stride 80B (40 bf16) -> ldmatrix conflict-free. Double buffered.
// grid = (N/128=4, M/128=256, 3 projections)
// ---------------------------------------------------------------------------
struct GemmArgs {
    const __nv_bfloat16* Ahi[3];
    const __nv_bfloat16* Alo[3];
    const __nv_bfloat16* Whi[3];
    const __nv_bfloat16* Wlo[3];
    const float* bias[3];
    float* out[3];
};

#define MAT_BYTES  10240                // 128 rows * 80B
#define STAGE_B    (4 * MAT_BYTES)      // 40960
#define GEMM_SMEM  (2 * STAGE_B)        // 81920

__device__ __forceinline__ void load_stage(uint32_t st,
                                           const __nv_bfloat16* const* src,
                                           const int* rb, int kc, int tid) {
#pragma unroll
    for (int a = 0; a < 4; a++) {
#pragma unroll
        for (int i = 0; i < 2; i++) {
            int c = tid + 256 * i;          // 0..511
            int row = c >> 2, q = c & 3;    // 128 rows x 4 16B-chunks
            cp16(st + a * MAT_BYTES + row * 80 + q * 16,
                 src[a] + (size_t)(rb[a] + row) * Dn + kc * 32 + q * 8);
        }
    }
    CP_COMMIT();
}

__global__ void __launch_bounds__(256) gemm_mma(GemmArgs args) {
    extern __shared__ char smem_raw[];
    uint32_t sbase = smem_u32(smem_raw);
    int tid = threadIdx.x;
    int wid = tid >> 5, lane = tid & 31;
    int warp_m = wid & 3;                 // 4 warps over M (32 rows each)
    int warp_n = wid >> 2;                // 2 warps over N (64 cols each)
    int z = blockIdx.z;
    int bn = blockIdx.x * 128;
    int bm = blockIdx.y * 128;

    const __nv_bfloat16* src[4] = {args.Ahi[z], args.Alo[z], args.Whi[z], args.Wlo[z]};
    int rb[4] = {bm, bm, bn, bn};

    float acc[2][8][4];
#pragma unroll
    for (int mt = 0; mt < 2; mt++)
#pragma unroll
        for (int nt = 0; nt < 8; nt++)
#pragma unroll
            for (int e = 0; e < 4; e++) acc[mt][nt][e] = 0.f;

    // ldmatrix lane addressing precomputed
    int a_row = lane & 15;                // rows 0..15
    int a_koff = (lane >> 4) * 16;        // byte offset: k half 0 / 8
    int g = lane >> 3;                    // B: 4 lane groups
    int b_nadd = ((g >> 1) & 1) * 8 + (lane & 7);
    int b_kadd = (g & 1) * 8;             // elements

    load_stage(sbase, src, rb, 0, tid);

#pragma unroll 1
    for (int s = 0; s < 16; s++) {
        if (s < 15) {
            load_stage(sbase + (uint32_t)((s + 1) & 1) * STAGE_B, src, rb, s + 1, tid);
            asm volatile("cp.async.wait_group 1;\n" ::: "memory");
        } else {
            asm volatile("cp.async.wait_group 0;\n" ::: "memory");
        }
        __syncthreads();
        uint32_t st = sbase + (uint32_t)(s & 1) * STAGE_B;

#pragma unroll
        for (int ks = 0; ks < 32; ks += 16) {
            uint32_t aH[2][4], aL[2][4], bH[8][2], bL[8][2];
#pragma unroll
            for (int mt = 0; mt < 2; mt++) {
                uint32_t ar = st + (uint32_t)((warp_m * 32 + mt * 16 + a_row) * 80)
                            + a_koff + ks * 2;
                ldsm_x4(aH[mt], ar);
                ldsm_x4(aL[mt], ar + MAT_BYTES);
            }
#pragma unroll
            for (int ntp = 0; ntp < 4; ntp++) {
                uint32_t br = st + 2 * MAT_BYTES
                            + (uint32_t)((warp_n * 64 + ntp * 16 + b_nadd) * 80)
                            + (ks + b_kadd) * 2;
                uint32_t t0[4], t1[4];
                ldsm_x4(t0, br);
                ldsm_x4(t1, br + MAT_BYTES);
                bH[2 * ntp][0] = t0[0]; bH[2 * ntp][1] = t0[1];
                bH[2 * ntp + 1][0] = t0[2]; bH[2 * ntp + 1][1] = t0[3];
                bL[2 * ntp][0] = t1[0]; bL[2 * ntp][1] = t1[1];
                bL[2 * ntp + 1][0] = t1[2]; bL[2 * ntp + 1][1] = t1[3];
            }
#pragma unroll
            for (int mt = 0; mt < 2; mt++)
#pragma unroll
                for (int nt = 0; nt < 8; nt++) {
                    mma16816(acc[mt][nt], aH[mt], bH[nt]);
                    mma16816(acc[mt][nt], aH[mt], bL[nt]);
                    mma16816(acc[mt][nt], aL[mt], bH[nt]);
                }
        }
        __syncthreads();
    }

    // Epilogue: c-fragment thread mapping: row = lane/4 (+8), col = (lane%4)*2 (+1)
    const float* bias = args.bias[z];
    float* out = args.out[z];
    int r = lane >> 2, c2 = (lane & 3) * 2;
#pragma unroll
    for (int mt = 0; mt < 2; mt++) {
#pragma unroll
        for (int nt = 0; nt < 8; nt++) {
            int col = bn + warp_n * 64 + nt * 8 + c2;
            float2 bb = *(const float2*)(bias + col);
            int row0 = bm + warp_m * 32 + mt * 16 + r;
            float2 o0, o1;
            o0.x = acc[mt][nt][0] + bb.x; o0.y = acc[mt][nt][1] + bb.y;
            o1.x = acc[mt][nt][2] + bb.x; o1.y = acc[mt][nt][3] + bb.y;
            *(float2*)(out + (size_t)row0 * Dn + col) = o0;
            *(float2*)(out + (size_t)(row0 + 8) * Dn + col) = o1;
        }
    }
}

// ---------------------------------------------------------------------------
// Causal flash attention (fp32, unchanged — known good)
// ---------------------------------------------------------------------------
#define ATTN_SMEM (4 * 64 * 68 * 4)

__global__ void __launch_bounds__(256) attn_kernel(const float* __restrict__ queries,
                                                   float* __restrict__ out) {
    extern __shared__ float sm[];
    float* Qs = sm;                   // [k][r], stride 68
    float* Ks = sm + 64 * 68;         // [k][c]
    float* Vs = sm + 2 * 64 * 68;     // [j][d]
    float* Ps = sm + 3 * 64 * 68;     // [j][r]

    const int L = Ln, D = Dn;
    int qt = blockIdx.x, h = blockIdx.y, b = blockIdx.z;
    int tid = threadIdx.x;
    int ty = tid >> 4, tx = tid & 15;
    int r0 = ty * 4, c0 = tx * 4;
    int q0 = qt * 64;

    int lr = tid >> 2;
    int lk = (tid & 3) * 4;

    {
        const float* qr = g_Q + ((size_t)(b * L + q0 + lr)) * D + h * DHn;
#pragma unroll
        for (int i = 0; i < 4; i++) {
            int kk = lk + 16 * i;
            float4 v = *(const float4*)(qr + kk);
            Qs[(kk + 0) * 68 + lr] = v.x * 0.125f;
            Qs[(kk + 1) * 68 + lr] = v.y * 0.125f;
            Qs[(kk + 2) * 68 + lr] = v.z * 0.125f;
            Qs[(kk + 3) * 68 + lr] = v.w * 0.125f;
        }
    }

    float acc[4][4];
#pragma unroll
    for (int i = 0; i < 4; i++)
#pragma unroll
        for (int j = 0; j < 4; j++) acc[i][j] = 0.f;
    float mrow[4], lsum[4];
#pragma unroll
    for (int i = 0; i < 4; i++) { mrow[i] = -INFINITY; lsum[i] = 0.f; }

    int ntiles = qt + 1;
    for (int kt = 0; kt < ntiles; kt++) {
        int kg0 = kt * 64;
        __syncthreads();
        {
            const float* kr = g_K + ((size_t)(b * L + kg0 + lr)) * D + h * DHn;
            const float* vr = g_V + ((size_t)(b * L + kg0 + lr)) * D + h * DHn;
#pragma unroll
            for (int i = 0; i < 4; i++) {
                int kk = lk + 16 * i;
                float4 kv = *(const float4*)(kr + kk);
                Ks[(kk + 0) * 68 + lr] = kv.x;
                Ks[(kk + 1) * 68 + lr] = kv.y;
                Ks[(kk + 2) * 68 + lr] = kv.z;
                Ks[(kk + 3) * 68 + lr] = kv.w;
                float4 vv = *(const float4*)(vr + kk);
                *(float4*)&Vs[lr * 68 + kk] = vv;
            }
        }
        __syncthreads();

        float s[4][4];
#pragma unroll
        for (int i = 0; i < 4; i++)
#pragma unroll
            for (int j = 0; j < 4; j++) s[i][j] = 0.f;
#pragma unroll 8
        for (int k = 0; k < 64; k++) {
            float4 a = *(const float4*)&Qs[k * 68 + r0];
            float4 bb = *(const float4*)&Ks[k * 68 + c0];
            float av[4] = {a.x, a.y, a.z, a.w};
            float bv[4] = {bb.x, bb.y, bb.z, bb.w};
#pragma unroll
            for (int i = 0; i < 4; i++)
#pragma unroll
                for (int j = 0; j < 4; j++) s[i][j] += av[i] * bv[j];
        }

        bool diag = (kt == qt);
#pragma unroll
        for (int j = 0; j < 4; j++) {
            int jg = kg0 + c0 + j;
            float km = g_kmask[b * L + jg];
            bool kvalid = (km != 0.0f);
#pragma unroll
            for (int i = 0; i < 4; i++) {
                bool ok = kvalid && (!diag || jg <= (q0 + r0 + i));
                if (!ok) s[i][j] = NEGC;
            }
        }

#pragma unroll
        for (int i = 0; i < 4; i++) {
            float mx = fmaxf(fmaxf(s[i][0], s[i][1]), fmaxf(s[i][2], s[i][3]));
#pragma unroll
            for (int o = 8; o; o >>= 1) mx = fmaxf(mx, __shfl_xor_sync(0xffffffffu, mx, o));
            float mnew = fmaxf(mrow[i], mx);
            float corr = __expf(mrow[i] - mnew);
            mrow[i] = mnew;
            float ps = 0.f;
#pragma unroll
            for (int j = 0; j < 4; j++) {
                float p = __expf(s[i][j] - mnew);
                s[i][j] = p;
                ps += p;
            }
#pragma unroll
            for (int o = 8; o; o >>= 1) ps += __shfl_xor_sync(0xffffffffu, ps, o);
            lsum[i] = lsum[i] * corr + ps;
#pragma unroll
            for (int j = 0; j < 4; j++) acc[i][j] *= corr;
        }

#pragma unroll
        for (int j = 0; j < 4; j++) {
            float4 pv = make_float4(s[0][j], s[1][j], s[2][j], s[3][j]);
            *(float4*)&Ps[(c0 + j) * 68 + r0] = pv;
        }
        __syncthreads();

#pragma unroll 8
        for (int j = 0; j < 64; j++) {
            float4 p4 = *(const float4*)&Ps[j * 68 + r0];
            float4 v4 = *(const float4*)&Vs[j * 68 + c0];
            float pv[4] = {p4.x, p4.y, p4.z, p4.w};
            float vv[4] = {v4.x, v4.y, v4.z, v4.w};
#pragma unroll
            for (int i = 0; i < 4; i++)
#pragma unroll
                for (int jj = 0; jj < 4; jj++) acc[i][jj] += pv[i] * vv[jj];
        }
    }

#pragma unroll
    for (int i = 0; i < 4; i++) {
        int qg = q0 + r0 + i;
        float qm = g_qmask[b * L + qg];
        float f = qm / lsum[i];
        size_t off = ((size_t)(b * L + qg)) * D + h * DHn + c0;
        float4 rv = *(const float4*)(queries + off);
        float4 o;
        o.x = acc[i][0] * f + rv.x;
        o.y = acc[i][1] * f + rv.y;
        o.z = acc[i][2] * f + rv.z;
        o.w = acc[i][3] * f + rv.w;
        *(float4*)(out + off) = o;
    }
}

// ---------------------------------------------------------------------------
extern "C" void kernel_launch(void* const* d_in, const int* in_sizes, int n_in,
                              void* d_out, int out_size) {
    (void)in_sizes; (void)n_in; (void)out_size;
    const float* queries = (const float*)d_in[0];
    const float* keys    = (const float*)d_in[1];
    const float* Wq = (const float*)d_in[2];
    const float* bq = (const float*)d_in[3];
    const float* Wk = (const float*)d_in[4];
    const float* bk = (const float*)d_in[5];
    const float* Wv = (const float*)d_in[6];
    const float* bv = (const float*)d_in[7];
    float* out = (float*)d_out;

    float *qp, *kp, *vp;
    cudaGetSymbolAddress((void**)&qp, g_Q);
    cudaGetSymbolAddress((void**)&kp, g_K);
    cudaGetSymbolAddress((void**)&vp, g_V);
    __nv_bfloat16 *qhi, *qlo, *khi, *klo, *whi, *wlo;
    cudaGetSymbolAddress((void**)&qhi, g_qhi);
    cudaGetSymbolAddress((void**)&qlo, g_qlo);
    cudaGetSymbolAddress((void**)&khi, g_khi);
    cudaGetSymbolAddress((void**)&klo, g_klo);
    cudaGetSymbolAddress((void**)&whi, g_whi);
    cudaGetSymbolAddress((void**)&wlo, g_wlo);

    cudaFuncSetAttribute(attn_kernel,
                         cudaFuncAttributeMaxDynamicSharedMemorySize, ATTN_SMEM);
    cudaFuncSetAttribute(gemm_mma,
                         cudaFuncAttributeMaxDynamicSharedMemorySize, GEMM_SMEM);

    // masks
    mask_kernel<<<8192, 256>>>(queries, keys);

    // bf16 hi/lo splits
    int n4a = (int)(NELEM_A / 4);
    int n4w = (int)(NELEM_W / 4);
    cvt_kernel<<<(n4a + 255) / 256, 256>>>(queries, qhi, qlo, n4a);
    cvt_kernel<<<(n4a + 255) / 256, 256>>>(keys,    khi, klo, n4a);
    cvt_kernel<<<(n4w + 255) / 256, 256>>>(Wq, whi + 0 * NELEM_W, wlo + 0 * NELEM_W, n4w);
    cvt_kernel<<<(n4w + 255) / 256, 256>>>(Wk, whi + 1 * NELEM_W, wlo + 1 * NELEM_W, n4w);
    cvt_kernel<<<(n4w + 255) / 256, 256>>>(Wv, whi + 2 * NELEM_W, wlo + 2 * NELEM_W, n4w);

    // fused QKV projections on tensor cores (mma.sync bf16 split-3)
    GemmArgs ga;
    ga.Ahi[0] = qhi; ga.Alo[0] = qlo;
    ga.Ahi[1] = khi; ga.Alo[1] = klo;
    ga.Ahi[2] = khi; ga.Alo[2] = klo;
    ga.Whi[0] = whi + 0 * NELEM_W; ga.Wlo[0] = wlo + 0 * NELEM_W;
    ga.Whi[1] = whi + 1 * NELEM_W; ga.Wlo[1] = wlo + 1 * NELEM_W;
    ga.Whi[2] = whi + 2 * NELEM_W; ga.Wlo[2] = wlo + 2 * NELEM_W;
    ga.bias[0] = bq; ga.bias[1] = bk; ga.bias[2] = bv;
    ga.out[0] = qp;  ga.out[1] = kp;  ga.out[2] = vp;
    gemm_mma<<<dim3(4, 256, 3), 256, GEMM_SMEM>>>(ga);

    // attention + residual
    attn_kernel<<<dim3(16, 8, 32), 256, ATTN_SMEM>>>(queries, out);
}

// round 5
// speedup vs baseline: 2.0861x; 1.5782x over previous
#include <cuda_runtime.h>
#include <cuda_bf16.h>
#include <math.h>
#include <cstdint>

// Problem dims (fixed by reference)
#define Bn  32
#define Ln  1024
#define Dn  512
#define Hn  8
#define DHn 64

#define NEGC (-4294967295.0f)   // -2^32 + 1, matches reference padding value

// ---------------------------------------------------------------------------
// Scratch (allocation-free rule: static __device__ globals)
// ---------------------------------------------------------------------------
__device__ float g_kmask[Bn * Ln];
__device__ float g_qmask[Bn * Ln];

// bf16 split (hi+lo) copies of GEMM inputs
#define NELEM_A ((size_t)Bn * Ln * Dn)      // 16,777,216
#define NELEM_W ((size_t)Dn * Dn)           // 262,144
__device__ __nv_bfloat16 g_qhi[NELEM_A];
__device__ __nv_bfloat16 g_qlo[NELEM_A];
__device__ __nv_bfloat16 g_khi[NELEM_A];
__device__ __nv_bfloat16 g_klo[NELEM_A];
__device__ __nv_bfloat16 g_whi[3][NELEM_W];
__device__ __nv_bfloat16 g_wlo[3][NELEM_W];

// Projected Q/K/V, bf16 hi/lo, head-major layout [b][h][l][64].
// z: 0 = Q (pre-scaled by 1/8), 1 = K, 2 = V
__device__ __nv_bfloat16 g_prjh[3][NELEM_A];
__device__ __nv_bfloat16 g_prjl[3][NELEM_A];

// ---------------------------------------------------------------------------
// PTX helpers (sm_80-baseline only — tcgen05 does NOT assemble at .target
// sm_103 in this harness)
// ---------------------------------------------------------------------------
__device__ __forceinline__ uint32_t smem_u32(const void* p) {
    uint32_t a;
    asm("{ .reg .u64 t; cvta.to.shared.u64 t, %1; cvt.u32.u64 %0, t; }"
        : "=r"(a) : "l"(p));
    return a;
}
__device__ __forceinline__ void cp16(uint32_t dst, const void* src) {
    asm volatile("cp.async.cg.shared.global [%0], [%1], 16;\n"
                 :: "r"(dst), "l"(src) : "memory");
}
#define CP_COMMIT() asm volatile("cp.async.commit_group;\n" ::: "memory")

__device__ __forceinline__ void ldsm_x4(uint32_t* r, uint32_t addr) {
    asm volatile("ldmatrix.sync.aligned.m8n8.x4.shared.b16 {%0,%1,%2,%3}, [%4];"
                 : "=r"(r[0]), "=r"(r[1]), "=r"(r[2]), "=r"(r[3]) : "r"(addr));
}
__device__ __forceinline__ void ldsm_x4_t(uint32_t* r, uint32_t addr) {
    asm volatile("ldmatrix.sync.aligned.m8n8.x4.trans.shared.b16 {%0,%1,%2,%3}, [%4];"
                 : "=r"(r[0]), "=r"(r[1]), "=r"(r[2]), "=r"(r[3]) : "r"(addr));
}
__device__ __forceinline__ void mma16816(float* d, const uint32_t* a, const uint32_t* b) {
    asm volatile(
        "mma.sync.aligned.m16n8k16.row.col.f32.bf16.bf16.f32 "
        "{%0,%1,%2,%3}, {%4,%5,%6,%7}, {%8,%9}, {%0,%1,%2,%3};"
        : "+f"(d[0]), "+f"(d[1]), "+f"(d[2]), "+f"(d[3])
        : "r"(a[0]), "r"(a[1]), "r"(a[2]), "r"(a[3]), "r"(b[0]), "r"(b[1]));
}
__device__ __forceinline__ uint32_t pack_bf2(float a, float b) {
    __nv_bfloat162 t = __floats2bfloat162_rn(a, b);
    return *(uint32_t*)&t;
}

// ---------------------------------------------------------------------------
// Padding masks
// ---------------------------------------------------------------------------
__global__ void mask_kernel(const float* __restrict__ queries,
                            const float* __restrict__ keys) {
    int warp = (blockIdx.x * blockDim.x + threadIdx.x) >> 5;
    int lane = threadIdx.x & 31;
    int which = warp >> 15;
    int row = warp & (Bn * Ln - 1);
    const float* src = which ? keys : queries;
    const float4* p = (const float4*)(src + (size_t)row * Dn);
    float s = 0.f;
#pragma unroll
    for (int i = 0; i < 4; i++) {
        float4 v = p[lane + 32 * i];
        s += (v.x + v.y) + (v.z + v.w);
    }
#pragma unroll
    for (int o = 16; o; o >>= 1) s += __shfl_xor_sync(0xffffffffu, s, o);
    if (lane == 0) {
        float m = (s != 0.0f) ? 1.0f : 0.0f;
        if (which) g_kmask[row] = m; else g_qmask[row] = m;
    }
}

// ---------------------------------------------------------------------------
// fp32 -> bf16 (hi, lo) split
// ---------------------------------------------------------------------------
__global__ void cvt_kernel(const float* __restrict__ src,
                           __nv_bfloat16* __restrict__ hi,
                           __nv_bfloat16* __restrict__ lo, int n4) {
    int i = blockIdx.x * blockDim.x + threadIdx.x;
    if (i >= n4) return;
    float4 v = ((const float4*)src)[i];
    __nv_bfloat162 h0 = __floats2bfloat162_rn(v.x, v.y);
    __nv_bfloat162 h1 = __floats2bfloat162_rn(v.z, v.w);
    float2 f0 = __bfloat1622float2(h0);
    float2 f1 = __bfloat1622float2(h1);
    __nv_bfloat162 l0 = __floats2bfloat162_rn(v.x - f0.x, v.y - f0.y);
    __nv_bfloat162 l1 = __floats2bfloat162_rn(v.z - f1.x, v.w - f1.y);
    ((__nv_bfloat162*)hi)[2 * i + 0] = h0;
    ((__nv_bfloat162*)hi)[2 * i + 1] = h1;
    ((__nv_bfloat162*)lo)[2 * i + 0] = l0;
    ((__nv_bfloat162*)lo)[2 * i + 1] = l1;
}

// ---------------------------------------------------------------------------
// bf16-split GEMM (mma.sync): proj_z = A_z @ W_z^T + bias_z, then split to
// bf16 hi/lo in head-major layout [b][h][l][64]. Q (z=0) pre-scaled by 1/8.
// ---------------------------------------------------------------------------
#define MAT_BYTES  10240                // 128 rows * 80B
#define STAGE_B    (4 * MAT_BYTES)      // 40960
#define GEMM_SMEM  (2 * STAGE_B)        // 81920

__device__ __forceinline__ void load_stage(uint32_t st,
                                           const __nv_bfloat16* const* src,
                                           const int* rb, int kc, int tid) {
#pragma unroll
    for (int a = 0; a < 4; a++) {
#pragma unroll
        for (int i = 0; i < 2; i++) {
            int c = tid + 256 * i;
            int row = c >> 2, q = c & 3;
            cp16(st + a * MAT_BYTES + row * 80 + q * 16,
                 src[a] + (size_t)(rb[a] + row) * Dn + kc * 32 + q * 8);
        }
    }
    CP_COMMIT();
}

__global__ void __launch_bounds__(256) gemm_mma(const float* __restrict__ bq,
                                                const float* __restrict__ bk,
                                                const float* __restrict__ bv) {
    extern __shared__ char smem_raw[];
    uint32_t sbase = smem_u32(smem_raw);
    int tid = threadIdx.x;
    int wid = tid >> 5, lane = tid & 31;
    int warp_m = wid & 3;
    int warp_n = wid >> 2;
    int z = blockIdx.z;
    int bn = blockIdx.x * 128;
    int bm = blockIdx.y * 128;

    const __nv_bfloat16* src[4];
    src[0] = (z == 0) ? g_qhi : g_khi;
    src[1] = (z == 0) ? g_qlo : g_klo;
    src[2] = g_whi[z];
    src[3] = g_wlo[z];
    const float* bias = (z == 0) ? bq : (z == 1 ? bk : bv);
    float scale = (z == 0) ? 0.125f : 1.0f;
    __nv_bfloat16* Ohi = g_prjh[z];
    __nv_bfloat16* Olo = g_prjl[z];
    int rb[4] = {bm, bm, bn, bn};

    float acc[2][8][4];
#pragma unroll
    for (int mt = 0; mt < 2; mt++)
#pragma unroll
        for (int nt = 0; nt < 8; nt++)
#pragma unroll
            for (int e = 0; e < 4; e++) acc[mt][nt][e] = 0.f;

    int a_row = lane & 15;
    int a_koff = (lane >> 4) * 16;
    int g = lane >> 3;
    int b_nadd = ((g >> 1) & 1) * 8 + (lane & 7);
    int b_kadd = (g & 1) * 8;

    load_stage(sbase, src, rb, 0, tid);

#pragma unroll 1
    for (int s = 0; s < 16; s++) {
        if (s < 15) {
            load_stage(sbase + (uint32_t)((s + 1) & 1) * STAGE_B, src, rb, s + 1, tid);
            asm volatile("cp.async.wait_group 1;\n" ::: "memory");
        } else {
            asm volatile("cp.async.wait_group 0;\n" ::: "memory");
        }
        __syncthreads();
        uint32_t st = sbase + (uint32_t)(s & 1) * STAGE_B;

#pragma unroll
        for (int ks = 0; ks < 32; ks += 16) {
            uint32_t aH[2][4], aL[2][4], bH[8][2], bL[8][2];
#pragma unroll
            for (int mt = 0; mt < 2; mt++) {
                uint32_t ar = st + (uint32_t)((warp_m * 32 + mt * 16 + a_row) * 80)
                            + a_koff + ks * 2;
                ldsm_x4(aH[mt], ar);
                ldsm_x4(aL[mt], ar + MAT_BYTES);
            }
#pragma unroll
            for (int ntp = 0; ntp < 4; ntp++) {
                uint32_t br = st + 2 * MAT_BYTES
                            + (uint32_t)((warp_n * 64 + ntp * 16 + b_nadd) * 80)
                            + (ks + b_kadd) * 2;
                uint32_t t0[4], t1[4];
                ldsm_x4(t0, br);
                ldsm_x4(t1, br + MAT_BYTES);
                bH[2 * ntp][0] = t0[0]; bH[2 * ntp][1] = t0[1];
                bH[2 * ntp + 1][0] = t0[2]; bH[2 * ntp + 1][1] = t0[3];
                bL[2 * ntp][0] = t1[0]; bL[2 * ntp][1] = t1[1];
                bL[2 * ntp + 1][0] = t1[2]; bL[2 * ntp + 1][1] = t1[3];
            }
#pragma unroll
            for (int mt = 0; mt < 2; mt++)
#pragma unroll
                for (int nt = 0; nt < 8; nt++) {
                    mma16816(acc[mt][nt], aH[mt], bH[nt]);
                    mma16816(acc[mt][nt], aH[mt], bL[nt]);
                    mma16816(acc[mt][nt], aL[mt], bH[nt]);
                }
        }
        __syncthreads();
    }

    // Epilogue: bias, scale, bf16 hi/lo split, head-major store
    int r = lane >> 2, c2 = (lane & 3) * 2;
#pragma unroll
    for (int mt = 0; mt < 2; mt++) {
#pragma unroll
        for (int nt = 0; nt < 8; nt++) {
            int col = bn + warp_n * 64 + nt * 8 + c2;
            float2 bb = *(const float2*)(bias + col);
            int hh = col >> 6, dd = col & 63;
#pragma unroll
            for (int half = 0; half < 2; half++) {
                int row = bm + warp_m * 32 + mt * 16 + r + half * 8;
                int bb_i = row >> 10, ll = row & 1023;
                size_t dst = ((size_t)((bb_i * Hn + hh) * Ln + ll)) * 64 + dd;
                float v0 = (acc[mt][nt][2 * half + 0] + bb.x) * scale;
                float v1 = (acc[mt][nt][2 * half + 1] + bb.y) * scale;
                __nv_bfloat162 h2 = __floats2bfloat162_rn(v0, v1);
                float2 hf = __bfloat1622float2(h2);
                __nv_bfloat162 l2 = __floats2bfloat162_rn(v0 - hf.x, v1 - hf.y);
                *(__nv_bfloat162*)(Ohi + dst) = h2;
                *(__nv_bfloat162*)(Olo + dst) = l2;
            }
        }
    }
}

// ---------------------------------------------------------------------------
// Tensor-core causal flash attention (bf16 split-3 on both matmuls)
// CTA: 128 q-rows for one (b,h); 8 warps x 16 rows; K tiles of 64,
// double-buffered cp.async. fp32 online softmax in registers.
// ---------------------------------------------------------------------------
#define ROWB 144                       // 72 bf16 per row (ldmatrix conflict-free)
#define MATB (64 * ROWB)               // 9216
#define STG  (4 * MATB)                // Khi, Klo, Vhi, Vlo
#define ATTN_SMEM (2 * STG + 2 * 256)  // + kmask staging

__global__ void __launch_bounds__(256) attn_mma(const float* __restrict__ queries,
                                                float* __restrict__ out) {
    extern __shared__ char smraw[];
    uint32_t sb = smem_u32(smraw);
    int tid = threadIdx.x, wid = tid >> 5, lane = tid & 31;
    int qt = blockIdx.x, h = blockIdx.y, b = blockIdx.z;
    int bh = b * Hn + h;
    int wq0 = wid * 16;

    const __nv_bfloat16* Qh = g_prjh[0] + (size_t)bh * Ln * 64;
    const __nv_bfloat16* Ql = g_prjl[0] + (size_t)bh * Ln * 64;
    const __nv_bfloat16* Kh = g_prjh[1] + (size_t)bh * Ln * 64;
    const __nv_bfloat16* Kl = g_prjl[1] + (size_t)bh * Ln * 64;
    const __nv_bfloat16* Vh = g_prjh[2] + (size_t)bh * Ln * 64;
    const __nv_bfloat16* Vl = g_prjl[2] + (size_t)bh * Ln * 64;

    // ---- load Q tile (hi at 0, lo at 18432), then to A-fragments ----
#pragma unroll
    for (int i = 0; i < 4; i++) {
        int idx = tid + 256 * i;
        int row = idx >> 3, ch = idx & 7;
        cp16(sb + row * ROWB + ch * 16,
             Qh + (size_t)(qt * 128 + row) * 64 + ch * 8);
        cp16(sb + 18432 + row * ROWB + ch * 16,
             Ql + (size_t)(qt * 128 + row) * 64 + ch * 8);
    }
    CP_COMMIT();
    asm volatile("cp.async.wait_group 0;\n" ::: "memory");
    __syncthreads();

    uint32_t qfh[4][4], qfl[4][4];
#pragma unroll
    for (int dk = 0; dk < 4; dk++) {
        uint32_t ar = sb + (uint32_t)((wq0 + (lane & 15)) * ROWB)
                    + (uint32_t)((dk * 16 + (lane >> 4) * 8) * 2);
        ldsm_x4(qfh[dk], ar);
        ldsm_x4(qfl[dk], ar + 18432);
    }
    __syncthreads();

    float o[8][4];
#pragma unroll
    for (int nt = 0; nt < 8; nt++)
#pragma unroll
        for (int e = 0; e < 4; e++) o[nt][e] = 0.f;
    float mrow0 = -INFINITY, mrow1 = -INFINITY, lsum0 = 0.f, lsum1 = 0.f;

    int ntk = 2 * qt + 2;

    auto load_kv = [&](int kt2) {
        uint32_t st = sb + (uint32_t)(kt2 & 1) * STG;
        int kg0 = kt2 * 64;
        const __nv_bfloat16* srcs[4] = {Kh, Kl, Vh, Vl};
#pragma unroll
        for (int m = 0; m < 4; m++) {
#pragma unroll
            for (int i = 0; i < 2; i++) {
                int idx = tid + 256 * i;
                int row = idx >> 3, ch = idx & 7;
                cp16(st + m * MATB + row * ROWB + ch * 16,
                     srcs[m] + (size_t)(kg0 + row) * 64 + ch * 8);
            }
        }
        if (tid < 16)
            cp16(sb + 2 * STG + (uint32_t)(kt2 & 1) * 256 + tid * 16,
                 g_kmask + b * Ln + kg0 + tid * 4);
        CP_COMMIT();
    };

    load_kv(0);

    int c2 = (lane & 3) * 2, rr = lane >> 2;
    int row0 = qt * 128 + wq0 + rr, row1 = row0 + 8;

#pragma unroll 1
    for (int kt = 0; kt < ntk; kt++) {
        if (kt + 1 < ntk) {
            load_kv(kt + 1);
            asm volatile("cp.async.wait_group 1;\n" ::: "memory");
        } else {
            asm volatile("cp.async.wait_group 0;\n" ::: "memory");
        }
        __syncthreads();
        uint32_t st = sb + (uint32_t)(kt & 1) * STG;

        // ---- S = Q K^T ----
        float s[8][4];
#pragma unroll
        for (int nt = 0; nt < 8; nt++)
#pragma unroll
            for (int e = 0; e < 4; e++) s[nt][e] = 0.f;

#pragma unroll
        for (int dk = 0; dk < 4; dk++) {
#pragma unroll
            for (int ntp = 0; ntp < 4; ntp++) {
                uint32_t br = st
                    + (uint32_t)((ntp * 16 + (lane & 7) + ((lane >> 4) & 1) * 8) * ROWB)
                    + (uint32_t)((dk * 16 + ((lane >> 3) & 1) * 8) * 2);
                uint32_t th[4], tl[4];
                ldsm_x4(th, br);
                ldsm_x4(tl, br + MATB);
                mma16816(s[2 * ntp],     qfh[dk], &th[0]);
                mma16816(s[2 * ntp],     qfh[dk], &tl[0]);
                mma16816(s[2 * ntp],     qfl[dk], &th[0]);
                mma16816(s[2 * ntp + 1], qfh[dk], &th[2]);
                mma16816(s[2 * ntp + 1], qfh[dk], &tl[2]);
                mma16816(s[2 * ntp + 1], qfl[dk], &th[2]);
            }
        }

        // ---- masks ----
        const float* kmp = (const float*)(smraw + 2 * STG + (kt & 1) * 256);
        int kbase = kt * 64;
#pragma unroll
        for (int nt = 0; nt < 8; nt++) {
            int col = kbase + nt * 8 + c2;
            float km0 = kmp[nt * 8 + c2];
            float km1 = kmp[nt * 8 + c2 + 1];
            if (km0 == 0.f || col > row0)     s[nt][0] = NEGC;
            if (km1 == 0.f || col + 1 > row0) s[nt][1] = NEGC;
            if (km0 == 0.f || col > row1)     s[nt][2] = NEGC;
            if (km1 == 0.f || col + 1 > row1) s[nt][3] = NEGC;
        }

        // ---- online softmax (rows owned by quads) ----
        float mx0 = -INFINITY, mx1 = -INFINITY;
#pragma unroll
        for (int nt = 0; nt < 8; nt++) {
            mx0 = fmaxf(mx0, fmaxf(s[nt][0], s[nt][1]));
            mx1 = fmaxf(mx1, fmaxf(s[nt][2], s[nt][3]));
        }
        mx0 = fmaxf(mx0, __shfl_xor_sync(0xffffffffu, mx0, 1));
        mx0 = fmaxf(mx0, __shfl_xor_sync(0xffffffffu, mx0, 2));
        mx1 = fmaxf(mx1, __shfl_xor_sync(0xffffffffu, mx1, 1));
        mx1 = fmaxf(mx1, __shfl_xor_sync(0xffffffffu, mx1, 2));
        float mn0 = fmaxf(mrow0, mx0), mn1 = fmaxf(mrow1, mx1);
        float corr0 = __expf(mrow0 - mn0), corr1 = __expf(mrow1 - mn1);
        mrow0 = mn0; mrow1 = mn1;

        float ps0 = 0.f, ps1 = 0.f;
#pragma unroll
        for (int nt = 0; nt < 8; nt++) {
            s[nt][0] = __expf(s[nt][0] - mn0);
            s[nt][1] = __expf(s[nt][1] - mn0);
            s[nt][2] = __expf(s[nt][2] - mn1);
            s[nt][3] = __expf(s[nt][3] - mn1);
            ps0 += s[nt][0] + s[nt][1];
            ps1 += s[nt][2] + s[nt][3];
        }
        ps0 += __shfl_xor_sync(0xffffffffu, ps0, 1);
        ps0 += __shfl_xor_sync(0xffffffffu, ps0, 2);
        ps1 += __shfl_xor_sync(0xffffffffu, ps1, 1);
        ps1 += __shfl_xor_sync(0xffffffffu, ps1, 2);
        lsum0 = lsum0 * corr0 + ps0;
        lsum1 = lsum1 * corr1 + ps1;
#pragma unroll
        for (int nt = 0; nt < 8; nt++) {
            o[nt][0] *= corr0; o[nt][1] *= corr0;
            o[nt][2] *= corr1; o[nt][3] *= corr1;
        }

        // ---- O += P V ----
        // P A-fragments pack directly from S C-fragments:
        // a0 = P[r][klow c2,c2+1]   = s[2ks][0..1]
        // a1 = P[r+8][klow]         = s[2ks][2..3]
        // a2 = P[r][khigh]          = s[2ks+1][0..1]
        // a3 = P[r+8][khigh]        = s[2ks+1][2..3]
        // (C-frag order already matches mma A-frag order — NO swap.)
#pragma unroll
        for (int ks = 0; ks < 4; ks++) {
            uint32_t aH[4], aL[4];
#pragma unroll
            for (int half = 0; half < 2; half++) {
                int nt = 2 * ks + half;
                float p0 = s[nt][0], p1 = s[nt][1], p2 = s[nt][2], p3 = s[nt][3];
                __nv_bfloat162 h01 = __floats2bfloat162_rn(p0, p1);
                __nv_bfloat162 h23 = __floats2bfloat162_rn(p2, p3);
                float2 f01 = __bfloat1622float2(h01);
                float2 f23 = __bfloat1622float2(h23);
                aH[2 * half + 0] = *(uint32_t*)&h01;
                aH[2 * half + 1] = *(uint32_t*)&h23;
                aL[2 * half + 0] = pack_bf2(p0 - f01.x, p1 - f01.y);
                aL[2 * half + 1] = pack_bf2(p2 - f23.x, p3 - f23.y);
            }
#pragma unroll
            for (int ntp = 0; ntp < 4; ntp++) {
                uint32_t br = st + 2 * MATB
                    + (uint32_t)((ks * 16 + (lane & 7) + ((lane >> 3) & 1) * 8) * ROWB)
                    + (uint32_t)((ntp * 16 + ((lane >> 4) & 1) * 8) * 2);
                uint32_t vh[4], vl[4];
                ldsm_x4_t(vh, br);
                ldsm_x4_t(vl, br + MATB);
                mma16816(o[2 * ntp],     aH, &vh[0]);
                mma16816(o[2 * ntp],     aH, &vl[0]);
                mma16816(o[2 * ntp],     aL, &vh[0]);
                mma16816(o[2 * ntp + 1], aH, &vh[2]);
                mma16816(o[2 * ntp + 1], aH, &vl[2]);
                mma16816(o[2 * ntp + 1], aL, &vh[2]);
            }
        }
        __syncthreads();
    }

    // ---- epilogue: normalize, query mask, residual, fp32 store ----
    float qm0 = g_qmask[b * Ln + row0];
    float qm1 = g_qmask[b * Ln + row1];
    float f0 = qm0 / lsum0, f1 = qm1 / lsum1;
    size_t base0 = ((size_t)(b * Ln + row0)) * Dn + h * 64;
    size_t base1 = ((size_t)(b * Ln + row1)) * Dn + h * 64;
#pragma unroll
    for (int nt = 0; nt < 8; nt++) {
        int d = nt * 8 + c2;
        float2 r0v = *(const float2*)(queries + base0 + d);
        float2 r1v = *(const float2*)(queries + base1 + d);
        float2 o0, o1;
        o0.x = o[nt][0] * f0 + r0v.x; o0.y = o[nt][1] * f0 + r0v.y;
        o1.x = o[nt][2] * f1 + r1v.x; o1.y = o[nt][3] * f1 + r1v.y;
        *(float2*)(out + base0 + d) = o0;
        *(float2*)(out + base1 + d) = o1;
    }
}

// ---------------------------------------------------------------------------
extern "C" void kernel_launch(void* const* d_in, const int* in_sizes, int n_in,
                              void* d_out, int out_size) {
    (void)in_sizes; (void)n_in; (void)out_size;
    const float* queries = (const float*)d_in[0];
    const float* keys    = (const float*)d_in[1];
    const float* Wq = (const float*)d_in[2];
    const float* bq = (const float*)d_in[3];
    const float* Wk = (const float*)d_in[4];
    const float* bk = (const float*)d_in[5];
    const float* Wv = (const float*)d_in[6];
    const float* bv = (const float*)d_in[7];
    float* out = (float*)d_out;

    __nv_bfloat16 *qhi, *qlo, *khi, *klo, *whi, *wlo;
    cudaGetSymbolAddress((void**)&qhi, g_qhi);
    cudaGetSymbolAddress((void**)&qlo, g_qlo);
    cudaGetSymbolAddress((void**)&khi, g_khi);
    cudaGetSymbolAddress((void**)&klo, g_klo);
    cudaGetSymbolAddress((void**)&whi, g_whi);
    cudaGetSymbolAddress((void**)&wlo, g_wlo);

    cudaFuncSetAttribute(gemm_mma,
                         cudaFuncAttributeMaxDynamicSharedMemorySize, GEMM_SMEM);
    cudaFuncSetAttribute(attn_mma,
                         cudaFuncAttributeMaxDynamicSharedMemorySize, ATTN_SMEM);

    // masks
    mask_kernel<<<8192, 256>>>(queries, keys);

    // bf16 hi/lo splits of GEMM inputs
    int n4a = (int)(NELEM_A / 4);
    int n4w = (int)(NELEM_W / 4);
    cvt_kernel<<<(n4a + 255) / 256, 256>>>(queries, qhi, qlo, n4a);
    cvt_kernel<<<(n4a + 255) / 256, 256>>>(keys,    khi, klo, n4a);
    cvt_kernel<<<(n4w + 255) / 256, 256>>>(Wq, whi + 0 * NELEM_W, wlo + 0 * NELEM_W, n4w);
    cvt_kernel<<<(n4w + 255) / 256, 256>>>(Wk, whi + 1 * NELEM_W, wlo + 1 * NELEM_W, n4w);
    cvt_kernel<<<(n4w + 255) / 256, 256>>>(Wv, whi + 2 * NELEM_W, wlo + 2 * NELEM_W, n4w);

    // QKV projections (tensor cores), bf16 hi/lo head-major outputs
    gemm_mma<<<dim3(4, 256, 3), 256, GEMM_SMEM>>>(bq, bk, bv);

    // tensor-core attention + residual
    attn_mma<<<dim3(8, 8, 32), 256, ATTN_SMEM>>>(queries, out);
}

// round 6
// speedup vs baseline: 2.4923x; 1.1947x over previous
#include <cuda_runtime.h>
#include <cuda_bf16.h>
#include <math.h>
#include <cstdint>

// Problem dims (fixed by reference)
#define Bn  32
#define Ln  1024
#define Dn  512
#define Hn  8
#define DHn 64

#define NEGC (-4294967295.0f)   // -2^32 + 1, matches reference padding value

// ---------------------------------------------------------------------------
// Scratch (allocation-free rule: static __device__ globals)
// ---------------------------------------------------------------------------
__device__ float g_kmask[Bn * Ln];
__device__ float g_qmask[Bn * Ln];

#define NELEM_A ((size_t)Bn * Ln * Dn)      // 16,777,216
#define NELEM_W ((size_t)Dn * Dn)           // 262,144
__device__ __nv_bfloat16 g_qhi[NELEM_A];
__device__ __nv_bfloat16 g_qlo[NELEM_A];
__device__ __nv_bfloat16 g_khi[NELEM_A];
__device__ __nv_bfloat16 g_klo[NELEM_A];
__device__ __nv_bfloat16 g_whi[3][NELEM_W];
__device__ __nv_bfloat16 g_wlo[3][NELEM_W];

// Projected Q/K/V, bf16 hi/lo, head-major layout [b][h][l][64].
// z: 0 = Q (pre-scaled by 1/8), 1 = K, 2 = V
__device__ __nv_bfloat16 g_prjh[3][NELEM_A];
__device__ __nv_bfloat16 g_prjl[3][NELEM_A];

// ---------------------------------------------------------------------------
// PTX helpers (sm_80-baseline only — tcgen05 does NOT assemble at .target
// sm_103 in this harness)
// ---------------------------------------------------------------------------
__device__ __forceinline__ uint32_t smem_u32(const void* p) {
    uint32_t a;
    asm("{ .reg .u64 t; cvta.to.shared.u64 t, %1; cvt.u32.u64 %0, t; }"
        : "=r"(a) : "l"(p));
    return a;
}
__device__ __forceinline__ void cp16(uint32_t dst, const void* src) {
    asm volatile("cp.async.cg.shared.global [%0], [%1], 16;\n"
                 :: "r"(dst), "l"(src) : "memory");
}
#define CP_COMMIT() asm volatile("cp.async.commit_group;\n" ::: "memory")

__device__ __forceinline__ void ldsm_x4(uint32_t* r, uint32_t addr) {
    asm volatile("ldmatrix.sync.aligned.m8n8.x4.shared.b16 {%0,%1,%2,%3}, [%4];"
                 : "=r"(r[0]), "=r"(r[1]), "=r"(r[2]), "=r"(r[3]) : "r"(addr));
}
__device__ __forceinline__ void ldsm_x4_t(uint32_t* r, uint32_t addr) {
    asm volatile("ldmatrix.sync.aligned.m8n8.x4.trans.shared.b16 {%0,%1,%2,%3}, [%4];"
                 : "=r"(r[0]), "=r"(r[1]), "=r"(r[2]), "=r"(r[3]) : "r"(addr));
}
__device__ __forceinline__ void mma16816(float* d, const uint32_t* a, const uint32_t* b) {
    asm volatile(
        "mma.sync.aligned.m16n8k16.row.col.f32.bf16.bf16.f32 "
        "{%0,%1,%2,%3}, {%4,%5,%6,%7}, {%8,%9}, {%0,%1,%2,%3};"
        : "+f"(d[0]), "+f"(d[1]), "+f"(d[2]), "+f"(d[3])
        : "r"(a[0]), "r"(a[1]), "r"(a[2]), "r"(a[3]), "r"(b[0]), "r"(b[1]));
}
__device__ __forceinline__ uint32_t pack_bf2(float a, float b) {
    __nv_bfloat162 t = __floats2bfloat162_rn(a, b);
    return *(uint32_t*)&t;
}

// ---------------------------------------------------------------------------
// Fused conversion + padding masks. One warp per 512-elem row.
// Rows 0..32767: queries; 32768..65535: keys; 65536..67071: W rows (3x512).
// ---------------------------------------------------------------------------
__global__ void __launch_bounds__(256) cvt_all(const float* __restrict__ q,
                                               const float* __restrict__ k,
                                               const float* __restrict__ Wq,
                                               const float* __restrict__ Wk,
                                               const float* __restrict__ Wv) {
    int w = blockIdx.x * 8 + (threadIdx.x >> 5);
    int lane = threadIdx.x & 31;
    const float* src;
    __nv_bfloat16 *hi, *lo;
    float* maskp = nullptr;
    if (w < 65536) {
        int row = w & 32767;
        size_t off = (size_t)row * Dn;
        if (w < 32768) {
            src = q + off; hi = g_qhi + off; lo = g_qlo + off;
            maskp = g_qmask + row;
        } else {
            src = k + off; hi = g_khi + off; lo = g_klo + off;
            maskp = g_kmask + row;
        }
    } else {
        int r = w - 65536;
        int z = r >> 9, row = r & 511;
        size_t off = (size_t)row * Dn;
        src = (z == 0 ? Wq : (z == 1 ? Wk : Wv)) + off;
        hi = g_whi[z] + off; lo = g_wlo[z] + off;
    }
    float s = 0.f;
#pragma unroll
    for (int i = 0; i < 4; i++) {
        int f = lane + 32 * i;
        float4 v = ((const float4*)src)[f];
        s += (v.x + v.y) + (v.z + v.w);
        __nv_bfloat162 h0 = __floats2bfloat162_rn(v.x, v.y);
        __nv_bfloat162 h1 = __floats2bfloat162_rn(v.z, v.w);
        float2 f0 = __bfloat1622float2(h0);
        float2 f1 = __bfloat1622float2(h1);
        __nv_bfloat162 l0 = __floats2bfloat162_rn(v.x - f0.x, v.y - f0.y);
        __nv_bfloat162 l1 = __floats2bfloat162_rn(v.z - f1.x, v.w - f1.y);
        ((__nv_bfloat162*)hi)[2 * f + 0] = h0;
        ((__nv_bfloat162*)hi)[2 * f + 1] = h1;
        ((__nv_bfloat162*)lo)[2 * f + 0] = l0;
        ((__nv_bfloat162*)lo)[2 * f + 1] = l1;
    }
    if (maskp) {
#pragma unroll
        for (int o = 16; o; o >>= 1) s += __shfl_xor_sync(0xffffffffu, s, o);
        if (lane == 0) *maskp = (s != 0.0f) ? 1.0f : 0.0f;
    }
}

// ---------------------------------------------------------------------------
// bf16-split GEMM (mma.sync): proj_z = A_z @ W_z^T + bias_z -> bf16 hi/lo,
// head-major [b][h][l][64]; Q pre-scaled by 1/8.
// CTA tile 256x128, 8 warps (4 over M x 2 over N), warp tile 64x64.
// K chunks of 32, 2-stage cp.async. grid = (4, 128, 3).
// ---------------------------------------------------------------------------
#define MATA   20480                 // 256 rows * 80B
#define MATW   10240                 // 128 rows * 80B
#define STAGE_B (2 * MATA + 2 * MATW)  // 61440
#define GEMM_SMEM (2 * STAGE_B)        // 122880

__device__ __forceinline__ void load_stage(uint32_t st,
                                           const __nv_bfloat16* Ahi,
                                           const __nv_bfloat16* Alo,
                                           const __nv_bfloat16* Whi,
                                           const __nv_bfloat16* Wlo,
                                           int bm, int bn, int kc, int tid) {
    const __nv_bfloat16* as[2] = {Ahi, Alo};
#pragma unroll
    for (int a = 0; a < 2; a++) {
#pragma unroll
        for (int i = 0; i < 4; i++) {
            int idx = tid + 256 * i;            // 0..1023
            int row = idx >> 2, q4 = idx & 3;
            cp16(st + a * MATA + row * 80 + q4 * 16,
                 as[a] + (size_t)(bm + row) * Dn + kc * 32 + q4 * 8);
        }
    }
    const __nv_bfloat16* ws[2] = {Whi, Wlo};
#pragma unroll
    for (int a = 0; a < 2; a++) {
#pragma unroll
        for (int i = 0; i < 2; i++) {
            int idx = tid + 256 * i;            // 0..511
            int row = idx >> 2, q4 = idx & 3;
            cp16(st + 2 * MATA + a * MATW + row * 80 + q4 * 16,
                 ws[a] + (size_t)(bn + row) * Dn + kc * 32 + q4 * 8);
        }
    }
    CP_COMMIT();
}

__global__ void __launch_bounds__(256, 1) gemm_mma(const float* __restrict__ bq,
                                                   const float* __restrict__ bk,
                                                   const float* __restrict__ bv) {
    extern __shared__ char smem_raw[];
    uint32_t sbase = smem_u32(smem_raw);
    int tid = threadIdx.x;
    int wid = tid >> 5, lane = tid & 31;
    int wm = wid & 3;                 // 4 warps over M (64 rows each)
    int wn = wid >> 2;                // 2 warps over N (64 cols each)
    int z = blockIdx.z;
    int bn = blockIdx.x * 128;
    int bm = blockIdx.y * 256;

    const __nv_bfloat16* Ahi = (z == 0) ? g_qhi : g_khi;
    const __nv_bfloat16* Alo = (z == 0) ? g_qlo : g_klo;
    const __nv_bfloat16* Whi = g_whi[z];
    const __nv_bfloat16* Wlo = g_wlo[z];
    const float* bias = (z == 0) ? bq : (z == 1 ? bk : bv);
    float scale = (z == 0) ? 0.125f : 1.0f;
    __nv_bfloat16* Ohi = g_prjh[z];
    __nv_bfloat16* Olo = g_prjl[z];

    float acc[4][8][4];
#pragma unroll
    for (int mt = 0; mt < 4; mt++)
#pragma unroll
        for (int nt = 0; nt < 8; nt++)
#pragma unroll
            for (int e = 0; e < 4; e++) acc[mt][nt][e] = 0.f;

    int a_row = lane & 15;
    int a_koff = (lane >> 4) * 16;
    int g = lane >> 3;
    int b_nadd = ((g >> 1) & 1) * 8 + (lane & 7);
    int b_kadd = (g & 1) * 8;

    load_stage(sbase, Ahi, Alo, Whi, Wlo, bm, bn, 0, tid);

#pragma unroll 1
    for (int s = 0; s < 16; s++) {
        if (s < 15) {
            load_stage(sbase + (uint32_t)((s + 1) & 1) * STAGE_B,
                       Ahi, Alo, Whi, Wlo, bm, bn, s + 1, tid);
            asm volatile("cp.async.wait_group 1;\n" ::: "memory");
        } else {
            asm volatile("cp.async.wait_group 0;\n" ::: "memory");
        }
        __syncthreads();
        uint32_t st = sbase + (uint32_t)(s & 1) * STAGE_B;

#pragma unroll
        for (int ks = 0; ks < 32; ks += 16) {
            uint32_t aH[4][4], aL[4][4], bH[8][2], bL[8][2];
#pragma unroll
            for (int mt = 0; mt < 4; mt++) {
                uint32_t ar = st + (uint32_t)((wm * 64 + mt * 16 + a_row) * 80)
                            + a_koff + ks * 2;
                ldsm_x4(aH[mt], ar);
                ldsm_x4(aL[mt], ar + MATA);
            }
#pragma unroll
            for (int ntp = 0; ntp < 4; ntp++) {
                uint32_t br = st + 2 * MATA
                            + (uint32_t)((wn * 64 + ntp * 16 + b_nadd) * 80)
                            + (ks + b_kadd) * 2;
                uint32_t t0[4], t1[4];
                ldsm_x4(t0, br);
                ldsm_x4(t1, br + MATW);
                bH[2 * ntp][0] = t0[0]; bH[2 * ntp][1] = t0[1];
                bH[2 * ntp + 1][0] = t0[2]; bH[2 * ntp + 1][1] = t0[3];
                bL[2 * ntp][0] = t1[0]; bL[2 * ntp][1] = t1[1];
                bL[2 * ntp + 1][0] = t1[2]; bL[2 * ntp + 1][1] = t1[3];
            }
#pragma unroll
            for (int mt = 0; mt < 4; mt++)
#pragma unroll
                for (int nt = 0; nt < 8; nt++) {
                    mma16816(acc[mt][nt], aH[mt], bH[nt]);
                    mma16816(acc[mt][nt], aH[mt], bL[nt]);
                    mma16816(acc[mt][nt], aL[mt], bH[nt]);
                }
        }
        __syncthreads();
    }

    // Epilogue: bias, scale, bf16 hi/lo split, head-major store
    int r = lane >> 2, c2 = (lane & 3) * 2;
#pragma unroll
    for (int mt = 0; mt < 4; mt++) {
#pragma unroll
        for (int nt = 0; nt < 8; nt++) {
            int col = bn + wn * 64 + nt * 8 + c2;
            float2 bb = *(const float2*)(bias + col);
            int hh = col >> 6, dd = col & 63;
#pragma unroll
            for (int half = 0; half < 2; half++) {
                int row = bm + wm * 64 + mt * 16 + r + half * 8;
                int bb_i = row >> 10, ll = row & 1023;
                size_t dst = ((size_t)((bb_i * Hn + hh) * Ln + ll)) * 64 + dd;
                float v0 = (acc[mt][nt][2 * half + 0] + bb.x) * scale;
                float v1 = (acc[mt][nt][2 * half + 1] + bb.y) * scale;
                __nv_bfloat162 h2 = __floats2bfloat162_rn(v0, v1);
                float2 hf = __bfloat1622float2(h2);
                __nv_bfloat162 l2 = __floats2bfloat162_rn(v0 - hf.x, v1 - hf.y);
                *(__nv_bfloat162*)(Ohi + dst) = h2;
                *(__nv_bfloat162*)(Olo + dst) = l2;
            }
        }
    }
}

// ---------------------------------------------------------------------------
// Tensor-core causal flash attention (bf16 split-3 on both matmuls)
// CTA: 128 q-rows per (b,h); 4 warps x 32 rows (2 mt frag groups);
// K tiles of 64 double-buffered; Q in dedicated SMEM (re-ldsm per tile);
// fp32 online softmax in registers; qt launched descending (heavy first).
// ---------------------------------------------------------------------------
#define ROWB 144                       // 72 bf16 per row
#define MATB (64 * ROWB)               // 9216
#define STG  (4 * MATB)                // 36864 (Khi, Klo, Vhi, Vlo)
#define KMOFF (2 * STG)                // kmask staging (2 x 256B)
#define QOFF_H (KMOFF + 512)
#define QOFF_L (QOFF_H + 128 * ROWB)
#define ATTN_SMEM (QOFF_L + 128 * ROWB)   // 111104

__global__ void __launch_bounds__(128, 2) attn_mma(const float* __restrict__ queries,
                                                   float* __restrict__ out) {
    extern __shared__ char smraw[];
    uint32_t sb = smem_u32(smraw);
    int tid = threadIdx.x, wid = tid >> 5, lane = tid & 31;
    int qt = (int)gridDim.x - 1 - (int)blockIdx.x;   // heavy tiles first
    int h = blockIdx.y, b = blockIdx.z;
    int bh = b * Hn + h;
    int wq0 = wid * 32;

    const __nv_bfloat16* Qh = g_prjh[0] + (size_t)bh * Ln * 64;
    const __nv_bfloat16* Ql = g_prjl[0] + (size_t)bh * Ln * 64;
    const __nv_bfloat16* Kh = g_prjh[1] + (size_t)bh * Ln * 64;
    const __nv_bfloat16* Kl = g_prjl[1] + (size_t)bh * Ln * 64;
    const __nv_bfloat16* Vh = g_prjh[2] + (size_t)bh * Ln * 64;
    const __nv_bfloat16* Vl = g_prjl[2] + (size_t)bh * Ln * 64;

    // ---- Q tile into dedicated SMEM ----
#pragma unroll
    for (int i = 0; i < 8; i++) {
        int idx = tid + 128 * i;          // 0..1023
        int row = idx >> 3, ch = idx & 7;
        cp16(sb + QOFF_H + row * ROWB + ch * 16,
             Qh + (size_t)(qt * 128 + row) * 64 + ch * 8);
        cp16(sb + QOFF_L + row * ROWB + ch * 16,
             Ql + (size_t)(qt * 128 + row) * 64 + ch * 8);
    }
    CP_COMMIT();

    float o[2][8][4];
#pragma unroll
    for (int mt = 0; mt < 2; mt++)
#pragma unroll
        for (int nt = 0; nt < 8; nt++)
#pragma unroll
            for (int e = 0; e < 4; e++) o[mt][nt][e] = 0.f;
    float mrow[2][2], lsum[2][2];
#pragma unroll
    for (int mt = 0; mt < 2; mt++) {
        mrow[mt][0] = -INFINITY; mrow[mt][1] = -INFINITY;
        lsum[mt][0] = 0.f;       lsum[mt][1] = 0.f;
    }

    int ntk = 2 * qt + 2;

    auto load_kv = [&](int kt2) {
        uint32_t st = sb + (uint32_t)(kt2 & 1) * STG;
        int kg0 = kt2 * 64;
        const __nv_bfloat16* srcs[4] = {Kh, Kl, Vh, Vl};
#pragma unroll
        for (int m = 0; m < 4; m++) {
#pragma unroll
            for (int i = 0; i < 4; i++) {
                int idx = tid + 128 * i;   // 0..511
                int row = idx >> 3, ch = idx & 7;
                cp16(st + m * MATB + row * ROWB + ch * 16,
                     srcs[m] + (size_t)(kg0 + row) * 64 + ch * 8);
            }
        }
        if (tid < 16)
            cp16(sb + KMOFF + (uint32_t)(kt2 & 1) * 256 + tid * 16,
                 g_kmask + b * Ln + kg0 + tid * 4);
        CP_COMMIT();
    };

    load_kv(0);

    int c2 = (lane & 3) * 2, rr = lane >> 2;
    int rowq[2][2];
#pragma unroll
    for (int mt = 0; mt < 2; mt++) {
        rowq[mt][0] = qt * 128 + wq0 + mt * 16 + rr;
        rowq[mt][1] = rowq[mt][0] + 8;
    }

#pragma unroll 1
    for (int kt = 0; kt < ntk; kt++) {
        if (kt + 1 < ntk) {
            load_kv(kt + 1);
            asm volatile("cp.async.wait_group 1;\n" ::: "memory");
        } else {
            asm volatile("cp.async.wait_group 0;\n" ::: "memory");
        }
        __syncthreads();
        uint32_t st = sb + (uint32_t)(kt & 1) * STG;

        // ---- S = Q K^T ----
        float s[2][8][4];
#pragma unroll
        for (int mt = 0; mt < 2; mt++)
#pragma unroll
            for (int nt = 0; nt < 8; nt++)
#pragma unroll
                for (int e = 0; e < 4; e++) s[mt][nt][e] = 0.f;

#pragma unroll
        for (int dk = 0; dk < 4; dk++) {
            uint32_t qfh[2][4], qfl[2][4];
#pragma unroll
            for (int mt = 0; mt < 2; mt++) {
                uint32_t ar = sb + QOFF_H
                    + (uint32_t)((wq0 + mt * 16 + (lane & 15)) * ROWB)
                    + (uint32_t)((dk * 16 + (lane >> 4) * 8) * 2);
                ldsm_x4(qfh[mt], ar);
                ldsm_x4(qfl[mt], ar + (QOFF_L - QOFF_H));
            }
#pragma unroll
            for (int ntp = 0; ntp < 4; ntp++) {
                uint32_t br = st
                    + (uint32_t)((ntp * 16 + (lane & 7) + ((lane >> 4) & 1) * 8) * ROWB)
                    + (uint32_t)((dk * 16 + ((lane >> 3) & 1) * 8) * 2);
                uint32_t th[4], tl[4];
                ldsm_x4(th, br);
                ldsm_x4(tl, br + MATB);
#pragma unroll
                for (int mt = 0; mt < 2; mt++) {
                    mma16816(s[mt][2 * ntp],     qfh[mt], &th[0]);
                    mma16816(s[mt][2 * ntp],     qfh[mt], &tl[0]);
                    mma16816(s[mt][2 * ntp],     qfl[mt], &th[0]);
                    mma16816(s[mt][2 * ntp + 1], qfh[mt], &th[2]);
                    mma16816(s[mt][2 * ntp + 1], qfh[mt], &tl[2]);
                    mma16816(s[mt][2 * ntp + 1], qfl[mt], &th[2]);
                }
            }
        }

        // ---- masks ----
        const float* kmp = (const float*)(smraw + KMOFF + (kt & 1) * 256);
        int kbase = kt * 64;
#pragma unroll
        for (int nt = 0; nt < 8; nt++) {
            int col = kbase + nt * 8 + c2;
            float km0 = kmp[nt * 8 + c2];
            float km1 = kmp[nt * 8 + c2 + 1];
#pragma unroll
            for (int mt = 0; mt < 2; mt++) {
                if (km0 == 0.f || col > rowq[mt][0])     s[mt][nt][0] = NEGC;
                if (km1 == 0.f || col + 1 > rowq[mt][0]) s[mt][nt][1] = NEGC;
                if (km0 == 0.f || col > rowq[mt][1])     s[mt][nt][2] = NEGC;
                if (km1 == 0.f || col + 1 > rowq[mt][1]) s[mt][nt][3] = NEGC;
            }
        }

        // ---- online softmax ----
#pragma unroll
        for (int mt = 0; mt < 2; mt++) {
            float mx0 = -INFINITY, mx1 = -INFINITY;
#pragma unroll
            for (int nt = 0; nt < 8; nt++) {
                mx0 = fmaxf(mx0, fmaxf(s[mt][nt][0], s[mt][nt][1]));
                mx1 = fmaxf(mx1, fmaxf(s[mt][nt][2], s[mt][nt][3]));
            }
            mx0 = fmaxf(mx0, __shfl_xor_sync(0xffffffffu, mx0, 1));
            mx0 = fmaxf(mx0, __shfl_xor_sync(0xffffffffu, mx0, 2));
            mx1 = fmaxf(mx1, __shfl_xor_sync(0xffffffffu, mx1, 1));
            mx1 = fmaxf(mx1, __shfl_xor_sync(0xffffffffu, mx1, 2));
            float mn0 = fmaxf(mrow[mt][0], mx0), mn1 = fmaxf(mrow[mt][1], mx1);
            float corr0 = __expf(mrow[mt][0] - mn0), corr1 = __expf(mrow[mt][1] - mn1);
            mrow[mt][0] = mn0; mrow[mt][1] = mn1;

            float ps0 = 0.f, ps1 = 0.f;
#pragma unroll
            for (int nt = 0; nt < 8; nt++) {
                s[mt][nt][0] = __expf(s[mt][nt][0] - mn0);
                s[mt][nt][1] = __expf(s[mt][nt][1] - mn0);
                s[mt][nt][2] = __expf(s[mt][nt][2] - mn1);
                s[mt][nt][3] = __expf(s[mt][nt][3] - mn1);
                ps0 += s[mt][nt][0] + s[mt][nt][1];
                ps1 += s[mt][nt][2] + s[mt][nt][3];
            }
            ps0 += __shfl_xor_sync(0xffffffffu, ps0, 1);
            ps0 += __shfl_xor_sync(0xffffffffu, ps0, 2);
            ps1 += __shfl_xor_sync(0xffffffffu, ps1, 1);
            ps1 += __shfl_xor_sync(0xffffffffu, ps1, 2);
            lsum[mt][0] = lsum[mt][0] * corr0 + ps0;
            lsum[mt][1] = lsum[mt][1] * corr1 + ps1;
#pragma unroll
            for (int nt = 0; nt < 8; nt++) {
                o[mt][nt][0] *= corr0; o[mt][nt][1] *= corr0;
                o[mt][nt][2] *= corr1; o[mt][nt][3] *= corr1;
            }
        }

        // ---- O += P V  (C-frag order == A-frag order; V via ldsm.trans) ----
#pragma unroll
        for (int ks = 0; ks < 4; ks++) {
            uint32_t aH[2][4], aL[2][4];
#pragma unroll
            for (int mt = 0; mt < 2; mt++) {
#pragma unroll
                for (int half = 0; half < 2; half++) {
                    int nt = 2 * ks + half;
                    float p0 = s[mt][nt][0], p1 = s[mt][nt][1];
                    float p2 = s[mt][nt][2], p3 = s[mt][nt][3];
                    __nv_bfloat162 h01 = __floats2bfloat162_rn(p0, p1);
                    __nv_bfloat162 h23 = __floats2bfloat162_rn(p2, p3);
                    float2 f01 = __bfloat1622float2(h01);
                    float2 f23 = __bfloat1622float2(h23);
                    aH[mt][2 * half + 0] = *(uint32_t*)&h01;
                    aH[mt][2 * half + 1] = *(uint32_t*)&h23;
                    aL[mt][2 * half + 0] = pack_bf2(p0 - f01.x, p1 - f01.y);
                    aL[mt][2 * half + 1] = pack_bf2(p2 - f23.x, p3 - f23.y);
                }
            }
#pragma unroll
            for (int ntp = 0; ntp < 4; ntp++) {
                uint32_t br = st + 2 * MATB
                    + (uint32_t)((ks * 16 + (lane & 7) + ((lane >> 3) & 1) * 8) * ROWB)
                    + (uint32_t)((ntp * 16 + ((lane >> 4) & 1) * 8) * 2);
                uint32_t vh[4], vl[4];
                ldsm_x4_t(vh, br);
                ldsm_x4_t(vl, br + MATB);
#pragma unroll
                for (int mt = 0; mt < 2; mt++) {
                    mma16816(o[mt][2 * ntp],     aH[mt], &vh[0]);
                    mma16816(o[mt][2 * ntp],     aH[mt], &vl[0]);
                    mma16816(o[mt][2 * ntp],     aL[mt], &vh[0]);
                    mma16816(o[mt][2 * ntp + 1], aH[mt], &vh[2]);
                    mma16816(o[mt][2 * ntp + 1], aH[mt], &vl[2]);
                    mma16816(o[mt][2 * ntp + 1], aL[mt], &vh[2]);
                }
            }
        }
        __syncthreads();
    }

    // ---- epilogue: normalize, query mask, residual, fp32 store ----
#pragma unroll
    for (int mt = 0; mt < 2; mt++) {
        float qm0 = g_qmask[b * Ln + rowq[mt][0]];
        float qm1 = g_qmask[b * Ln + rowq[mt][1]];
        float f0 = qm0 / lsum[mt][0], f1 = qm1 / lsum[mt][1];
        size_t base0 = ((size_t)(b * Ln + rowq[mt][0])) * Dn + h * 64;
        size_t base1 = ((size_t)(b * Ln + rowq[mt][1])) * Dn + h * 64;
#pragma unroll
        for (int nt = 0; nt < 8; nt++) {
            int d = nt * 8 + c2;
            float2 r0v = *(const float2*)(queries + base0 + d);
            float2 r1v = *(const float2*)(queries + base1 + d);
            float2 o0, o1;
            o0.x = o[mt][nt][0] * f0 + r0v.x; o0.y = o[mt][nt][1] * f0 + r0v.y;
            o1.x = o[mt][nt][2] * f1 + r1v.x; o1.y = o[mt][nt][3] * f1 + r1v.y;
            *(float2*)(out + base0 + d) = o0;
            *(float2*)(out + base1 + d) = o1;
        }
    }
}

// ---------------------------------------------------------------------------
extern "C" void kernel_launch(void* const* d_in, const int* in_sizes, int n_in,
                              void* d_out, int out_size) {
    (void)in_sizes; (void)n_in; (void)out_size;
    const float* queries = (const float*)d_in[0];
    const float* keys    = (const float*)d_in[1];
    const float* Wq = (const float*)d_in[2];
    const float* bq = (const float*)d_in[3];
    const float* Wk = (const float*)d_in[4];
    const float* bk = (const float*)d_in[5];
    const float* Wv = (const float*)d_in[6];
    const float* bv = (const float*)d_in[7];
    float* out = (float*)d_out;

    cudaFuncSetAttribute(gemm_mma,
                         cudaFuncAttributeMaxDynamicSharedMemorySize, GEMM_SMEM);
    cudaFuncSetAttribute(attn_mma,
                         cudaFuncAttributeMaxDynamicSharedMemorySize, ATTN_SMEM);

    // 1) fused bf16 hi/lo splits + padding masks (one kernel)
    cvt_all<<<8384, 256>>>(queries, keys, Wq, Wk, Wv);

    // 2) QKV projections (tensor cores), bf16 hi/lo head-major outputs
    gemm_mma<<<dim3(4, 128, 3), 256, GEMM_SMEM>>>(bq, bk, bv);

    // 3) tensor-core attention + residual
    attn_mma<<<dim3(8, 8, 32), 128, ATTN_SMEM>>>(queries, out);
}